// round 17
// baseline (speedup 1.0000x reference)
#include <cuda_runtime.h>
#include <cstdint>

// Problem constants (from reference): B=32, S=1024, D=512
#define BB 32
#define SS 1024
#define DD 512
#define DV4 (DD / 4)     // 128 float4 per row
#define TAILW 64         // s-blocks per batch sharing the tail zero-fill
#define PERT (SS / 128)  // durations per scan thread = 8

// Scratch (allocation-free per harness rules)
__device__ int2 g_se[BB * SS];    // (start, end) per source row
__device__ int  g_totals[BB];     // total_lengths per batch

// ---------------------------------------------------------------------------
// Kernel A: per-batch duration round/clamp + inclusive scan -> (start,end).
// One block per batch, 128 threads, 8 durations/thread (2x float4).
// ---------------------------------------------------------------------------
__global__ void __launch_bounds__(128)
durscan_kernel(const float* __restrict__ durations, const int* __restrict__ scale_raw,
               float* __restrict__ len_out, int write_len)
{
    const int b   = blockIdx.x;
    const int tid = threadIdx.x;
    const int lane = tid & 31;
    const int warp = tid >> 5;

    // duration_scale dtype is ambiguous (python int 1 vs float 1.0).
    // Interpret the raw word as float if in a sane range, else as int.
    const int   iv = scale_raw[0];
    const float fvs = __int_as_float(iv);
    const float af = fabsf(fvs);
    const float scale = (af >= 1e-6f && af <= 1e6f) ? fvs : (float)iv;

    const float4* db4 = (const float4*)(durations + b * SS);
    const float4 a0 = __ldg(&db4[2 * tid]);
    const float4 a1 = __ldg(&db4[2 * tid + 1]);
    int d[PERT];
    d[0] = (int)(a0.x * scale + 0.5f); d[1] = (int)(a0.y * scale + 0.5f);
    d[2] = (int)(a0.z * scale + 0.5f); d[3] = (int)(a0.w * scale + 0.5f);
    d[4] = (int)(a1.x * scale + 0.5f); d[5] = (int)(a1.y * scale + 0.5f);
    d[6] = (int)(a1.z * scale + 0.5f); d[7] = (int)(a1.w * scale + 0.5f);
    int tsum = 0;
    #pragma unroll
    for (int i = 0; i < PERT; ++i) { if (d[i] < 1) d[i] = 1; tsum += d[i]; }

    // Inclusive scan of per-thread sums: warp shuffle + 4 warp partials.
    int w = tsum;
    #pragma unroll
    for (int o = 1; o < 32; o <<= 1) {
        int n = __shfl_up_sync(0xffffffffu, w, o);
        if (lane >= o) w += n;
    }
    __shared__ int wsum[4];
    if (lane == 31) wsum[warp] = w;
    __syncthreads();
    int base = w - tsum, tot = 0;
    #pragma unroll
    for (int k = 0; k < 4; ++k) {
        if (k < warp) base += wsum[k];
        tot += wsum[k];
    }

    // Emit (start, end) pairs: one 8B word per source row, int4-packed stores.
    int e = base;
    int4* sb = (int4*)(g_se + (size_t)b * SS + tid * PERT);
    int4 p01, p23, p45, p67;
    p01.x = e;        p01.y = e + d[0]; e = p01.y;
    p01.z = e;        p01.w = e + d[1]; e = p01.w;
    p23.x = e;        p23.y = e + d[2]; e = p23.y;
    p23.z = e;        p23.w = e + d[3]; e = p23.w;
    p45.x = e;        p45.y = e + d[4]; e = p45.y;
    p45.z = e;        p45.w = e + d[5]; e = p45.w;
    p67.x = e;        p67.y = e + d[6]; e = p67.y;
    p67.z = e;        p67.w = e + d[7]; e = p67.w;
    sb[0] = p01; sb[1] = p23; sb[2] = p45; sb[3] = p67;

    if (tid == 127) {
        g_totals[b] = tot;
        if (write_len) len_out[b] = (float)tot;
    }
}

// ---------------------------------------------------------------------------
// Kernel B: scatter-expand + fused tail zero-fill. (Best measured: 46.82us)
// One 128-thread block per (s, b) source row. Each thread holds one float4 of
// x[b][s] in a register and streams it to output rows [start, end).
// Single 8B pair load on the dependent path; store/tail loops unchanged.
// ---------------------------------------------------------------------------
__global__ void __launch_bounds__(128)
scatter_kernel(const float4* __restrict__ x4, float4* __restrict__ out4, int T)
{
    const int s = blockIdx.x;
    const int b = blockIdx.y;

    const int2 se = *(const int2*)&g_se[(size_t)b * SS + s];

    const float4 v = __ldcs(&x4[((size_t)b * SS + s) * DV4 + threadIdx.x]);

    float4* dst = out4 + ((size_t)b * T + se.x) * DV4 + threadIdx.x;
    for (int r = se.x; r < se.y; ++r) {
        __stcs(dst, v);
        dst += DV4;
    }

    // Fused tail zero-fill: rows [tot, T) shared across the last TAILW blocks.
    if (s >= SS - TAILW) {
        const int tot = g_totals[b];
        const float4 z = make_float4(0.f, 0.f, 0.f, 0.f);
        for (int r = tot + (s - (SS - TAILW)); r < T; r += TAILW) {
            __stcs(out4 + ((size_t)b * T + r) * DV4 + threadIdx.x, z);
        }
    }
}

// ---------------------------------------------------------------------------
extern "C" void kernel_launch(void* const* d_in, const int* in_sizes, int n_in,
                              void* d_out, int out_size)
{
    const float4* x4    = (const float4*)d_in[0];   // x: (B,S,D) float32
    const float*  dur   = (const float*)d_in[1];    // durations: (B,S) float32
    const int*    scale = (const int*)d_in[2];      // duration_scale: scalar
    float* out = (float*)d_out;

    // Recover T (max total length) from out_size:
    //   out only:           out_size = B*T*D
    //   out + lengths tail: out_size = B*T*D + B
    int T, has_len;
    if (out_size % (BB * DD) == 0) {
        T = out_size / (BB * DD);
        has_len = 0;
    } else {
        T = (out_size - BB) / (BB * DD);
        has_len = 1;
    }

    durscan_kernel<<<BB, 128>>>(dur, scale, out + (size_t)BB * T * DD, has_len);
    scatter_kernel<<<dim3(SS, BB), 128>>>(x4, (float4*)out, T);
}